// round 6
// baseline (speedup 1.0000x reference)
#include <cuda_runtime.h>
#include <cuda_fp16.h>
#include <cstdint>

// ---------------- problem constants ----------------
#define DH        2048
#define KTOT      4096            // concat(x,h) K
#define KC        64              // fp16 per K-chunk = 128 bytes (SW128 atom row)
#define KITERS    64              // 4096/64
#define NSTAGE    4
#define MT        128             // CTA M tile
#define NT        64              // CTA N tile
#define A_TILE_BYTES  (MT * 128)          // 16384
#define B_TILE_BYTES  (NT * 128)          // 8192  (per gate)
#define STAGE_BYTES   (A_TILE_BYTES + 3 * B_TILE_BYTES)   // 40960
#define SMEM_TOTAL    (1024 + NSTAGE * STAGE_BYTES)       // 164864

#define A_ELEMS   (8192u * 4096u)
#define W_ELEMS   (3u * 2048u * 4096u)
#define A_VEC4    (A_ELEMS / 4u)
#define TOT_VEC4  ((A_ELEMS + W_ELEMS) / 4u)

// ---------------- scratch (device globals: allocation-free rule) ----------------
__device__ __align__(1024) __half g_Ah[A_ELEMS];
__device__ __align__(1024) __half g_Wh[W_ELEMS];

// ---------------- helpers ----------------
static __device__ __forceinline__ uint32_t smem_u32(const void* p) {
    uint32_t a;
    asm("{ .reg .u64 t; cvta.to.shared.u64 t, %1; cvt.u32.u64 %0, t; }" : "=r"(a) : "l"(p));
    return a;
}
static __device__ __forceinline__ void cp16(uint32_t dst, const void* src) {
    asm volatile("cp.async.cg.shared.global [%0], [%1], 16;" :: "r"(dst), "l"(src) : "memory");
}
static __device__ __forceinline__ void ldsm4(uint32_t* r, uint32_t addr) {
    asm volatile("ldmatrix.sync.aligned.m8n8.x4.shared.b16 {%0,%1,%2,%3}, [%4];"
                 : "=r"(r[0]), "=r"(r[1]), "=r"(r[2]), "=r"(r[3]) : "r"(addr));
}
static __device__ __forceinline__ void mma16816(float* c4, const uint32_t* a,
                                                uint32_t b0, uint32_t b1) {
    asm volatile(
        "mma.sync.aligned.m16n8k16.row.col.f32.f16.f16.f32 "
        "{%0,%1,%2,%3}, {%4,%5,%6,%7}, {%8,%9}, {%0,%1,%2,%3};"
        : "+f"(c4[0]), "+f"(c4[1]), "+f"(c4[2]), "+f"(c4[3])
        : "r"(a[0]), "r"(a[1]), "r"(a[2]), "r"(a[3]), "r"(b0), "r"(b1));
}
static __device__ __forceinline__ float sigf(float x) {
    return __fdividef(1.f, 1.f + __expf(-x));
}
static __device__ __forceinline__ float tanhe(float x) {
    float t = __expf(2.f * x);
    return __fdividef(t - 1.f, t + 1.f);
}
static __device__ __forceinline__ uint32_t sw128(uint32_t off) {
    return off ^ ((off >> 3) & 0x70);
}

// ---------------- kernel 1: fp32 -> fp16 pack (K-concatenated layouts) ----------------
__global__ void __launch_bounds__(256)
lstm_conv_kernel(const float* __restrict__ x,   const float* __restrict__ h,
                 const float* __restrict__ Wix, const float* __restrict__ Wmx,
                 const float* __restrict__ Wox, const float* __restrict__ Wih,
                 const float* __restrict__ Wmh, const float* __restrict__ Woh)
{
    const size_t i = (size_t)blockIdx.x * 256 + threadIdx.x;   // vec4 index
    const float* src;
    __half* dst;
    if (i < A_VEC4) {
        size_t e = i << 2;                 // element in [0, A_ELEMS)
        size_t m = e >> 12, k = e & 4095;
        src = (k < 2048 ? x : h) + m * 2048 + (k & 2047);
        dst = g_Ah + e;
    } else {
        size_t e = (i - A_VEC4) << 2;      // element in [0, W_ELEMS)
        size_t g = e >> 23;                // each gate = 2^23 elems
        size_t r = e & 8388607;
        size_t n = r >> 12, k = r & 4095;
        const float* Wx = (g == 0 ? Wix : (g == 1 ? Wmx : Wox));
        const float* Wh2 = (g == 0 ? Wih : (g == 1 ? Wmh : Woh));
        src = (k < 2048 ? Wx : Wh2) + n * 2048 + (k & 2047);
        dst = g_Wh + e;
    }
    float4 v = *(const float4*)src;
    __half2 p0 = __floats2half2_rn(v.x, v.y);
    __half2 p1 = __floats2half2_rn(v.z, v.w);
    uint2 pk;
    pk.x = *(const uint32_t*)&p0;
    pk.y = *(const uint32_t*)&p1;
    *(uint2*)dst = pk;
}

// ---------------- kernel 2: fused 3-gate warp-MMA GEMM + LSTM epilogue ----------------
__global__ void __launch_bounds__(256, 1)
lstm_gemm_kernel(const float* __restrict__ c,
                 const float* __restrict__ bix, const float* __restrict__ bmx,
                 const float* __restrict__ box_,
                 const float* __restrict__ bih, const float* __restrict__ bmh,
                 const float* __restrict__ boh,
                 float* __restrict__ out)
{
    extern __shared__ char smem[];
    const uint32_t sb = smem_u32(smem);
    float* sbias = (float*)smem;                  // [3][64] gate bias sums
    // stages at sb + 1024 + st*STAGE_BYTES

    const int tid  = threadIdx.x;
    const int wid  = tid >> 5;
    const int lane = tid & 31;
    const int wm   = wid & 1;        // 2 warps along M (64 rows each)
    const int wn   = wid >> 1;       // 4 warps along N (16 cols each)

    const int n0 = (blockIdx.x & 31) << 6;    // n fastest -> W stays L2-resident
    const int m0 = (int)(blockIdx.x >> 5) << 7;

    if (tid < 192) {
        int g  = tid >> 6;
        int nl = tid & 63;
        int n  = n0 + nl;
        const float* bx = (g == 0 ? bix : (g == 1 ? bmx : box_));
        const float* bh = (g == 0 ? bih : (g == 1 ? bmh : boh));
        sbias[tid] = bx[n] + bh[n];
    }

    // ---- producer: each thread loads 10 x 16B chunks per stage ----
    auto load_stage = [&](int kc, int st) {
        const int k0 = kc * KC;
        const uint32_t stbase = sb + 1024 + (uint32_t)st * STAGE_BYTES;
#pragma unroll
        for (int t = 0; t < 10; ++t) {
            int ch = tid + t * 256;                  // 0..2559
            const __half* src;
            uint32_t dst;
            if (ch < 1024) {                         // A tile: 128 rows x 8 chunks
                int r  = ch >> 3;
                int cc = ch & 7;
                src = g_Ah + (size_t)(m0 + r) * 4096 + k0 + cc * 8;
                dst = stbase + sw128((uint32_t)((r << 7) + (cc << 4)));
            } else {                                 // B tiles: 3 x 64 rows x 8 chunks
                int b  = ch - 1024;
                int g  = b >> 9;                     // /512
                int r  = (b & 511) >> 3;
                int cc = b & 7;
                src = g_Wh + (size_t)g * 8388608u + (size_t)(n0 + r) * 4096 + k0 + cc * 8;
                dst = stbase + A_TILE_BYTES + (uint32_t)g * B_TILE_BYTES
                             + sw128((uint32_t)((r << 7) + (cc << 4)));
            }
            cp16(dst, src);
        }
        asm volatile("cp.async.commit_group;" ::: "memory");
    };

    // ---- accumulators: [gate][m16 block][n8 block][4] ----
    float acc[3][4][2][4];
#pragma unroll
    for (int g = 0; g < 3; ++g)
#pragma unroll
        for (int i = 0; i < 4; ++i)
#pragma unroll
            for (int j = 0; j < 2; ++j)
#pragma unroll
                for (int v = 0; v < 4; ++v) acc[g][i][j][v] = 0.f;

    // ---- consumer: one K-chunk of 64 from stage st ----
    auto compute_stage = [&](int st) {
        const uint32_t stbase = sb + 1024 + (uint32_t)st * STAGE_BYTES;
        const int rA = wm * 64 + (lane & 15);
        const int rB = wn * 16 + (lane & 15);
        const uint32_t kbl = (uint32_t)((lane >> 4) << 4);
#pragma unroll
        for (int ks = 0; ks < 4; ++ks) {
            const uint32_t kb = (uint32_t)(ks * 32) + kbl;
            uint32_t a[4][4];
#pragma unroll
            for (int i = 0; i < 4; ++i) {
                uint32_t off = (uint32_t)((rA + i * 16) << 7) + kb;
                ldsm4(a[i], stbase + sw128(off));
            }
#pragma unroll
            for (int g = 0; g < 3; ++g) {
                uint32_t b[4];
                uint32_t off = (uint32_t)(rB << 7) + kb;
                ldsm4(b, stbase + A_TILE_BYTES + (uint32_t)g * B_TILE_BYTES + sw128(off));
#pragma unroll
                for (int i = 0; i < 4; ++i) {
                    mma16816(acc[g][i][0], a[i], b[0], b[2]);
                    mma16816(acc[g][i][1], a[i], b[1], b[3]);
                }
            }
        }
    };

    // ---- pipeline ----
    load_stage(0, 0);
    load_stage(1, 1);
    load_stage(2, 2);

    for (int s = 0; s < KITERS; ++s) {
        if (s < KITERS - 2)       asm volatile("cp.async.wait_group 2;" ::: "memory");
        else if (s == KITERS - 2) asm volatile("cp.async.wait_group 1;" ::: "memory");
        else                      asm volatile("cp.async.wait_group 0;" ::: "memory");
        __syncthreads();
        if (s + 3 < KITERS) load_stage(s + 3, (s + 3) & 3);
        compute_stage(s & 3);
    }

    // ---- fused LSTM epilogue (fully register-local) ----
    const int quad = lane >> 2;
    const int tc   = lane & 3;
#pragma unroll
    for (int i = 0; i < 4; ++i) {
#pragma unroll
        for (int hh = 0; hh < 2; ++hh) {
            const int m = m0 + wm * 64 + i * 16 + quad + hh * 8;
            const float* crow = c   + (size_t)m * DH;
            float*       hrow = out + (size_t)m * DH;
            float*       nrow = out + (size_t)8192 * DH + (size_t)m * DH;
#pragma unroll
            for (int j = 0; j < 2; ++j) {
                const int nl = wn * 16 + j * 8 + tc * 2;
                const int n  = n0 + nl;
                float2 c2 = *(const float2*)(crow + n);
                float hn[2], cn[2];
#pragma unroll
                for (int e = 0; e < 2; ++e) {
                    float gi = acc[0][i][j][hh * 2 + e] + sbias[nl + e];
                    float gm = acc[1][i][j][hh * 2 + e] + sbias[64 + nl + e];
                    float go = acc[2][i][j][hh * 2 + e] + sbias[128 + nl + e];
                    float is = sigf(gi);
                    float fs = sigf(gm);
                    float ms = tanhe(gm);
                    float os = sigf(go);
                    float cold = (e == 0 ? c2.x : c2.y);
                    float cc = fs * cold + is * ms;
                    cn[e] = cc;
                    hn[e] = os * tanhe(cc);
                }
                *(float2*)(hrow + n) = make_float2(hn[0], hn[1]);
                *(float2*)(nrow + n) = make_float2(cn[0], cn[1]);
            }
        }
    }
}

// ---------------- launch ----------------
extern "C" void kernel_launch(void* const* d_in, const int* in_sizes, int n_in,
                              void* d_out, int out_size) {
    const float* x   = (const float*)d_in[0];
    const float* h   = (const float*)d_in[1];
    const float* c   = (const float*)d_in[2];
    const float* Wix = (const float*)d_in[3];
    const float* bix = (const float*)d_in[4];
    const float* Wmx = (const float*)d_in[5];
    const float* bmx = (const float*)d_in[6];
    const float* Wox = (const float*)d_in[7];
    const float* box_= (const float*)d_in[8];
    const float* Wih = (const float*)d_in[9];
    const float* bih = (const float*)d_in[10];
    const float* Wmh = (const float*)d_in[11];
    const float* bmh = (const float*)d_in[12];
    const float* Woh = (const float*)d_in[13];
    const float* boh = (const float*)d_in[14];
    float* out = (float*)d_out;

    cudaFuncSetAttribute(lstm_gemm_kernel,
                         cudaFuncAttributeMaxDynamicSharedMemorySize, SMEM_TOTAL);

    lstm_conv_kernel<<<TOT_VEC4 / 256, 256>>>(x, h, Wix, Wmx, Wox, Wih, Wmh, Woh);
    lstm_gemm_kernel<<<2048, 256, SMEM_TOTAL>>>(c, bix, bmx, box_, bih, bmh, boh, out);
}

// round 8
// speedup vs baseline: 1.0353x; 1.0353x over previous
#include <cuda_runtime.h>
#include <cuda_fp16.h>
#include <cstdint>

// ---------------- problem constants ----------------
#define DH        2048
#define KTOT      4096            // concat(x,h) K
#define KC        128             // fp16 per stage K-chunk (= 2 x 64 sub-chunks)
#define KITERS    32              // 4096/128
#define MT        128             // CTA M tile
#define NT        64              // CTA N tile
#define SUB_BYTES    40960        // A(16384) + 3 x B(8192), one 64-wide sub-chunk
#define STAGE_BYTES  81920        // 2 sub-chunks
#define SMEM_TOTAL   (1024 + 2 * STAGE_BYTES)     // 164864

#define A_ELEMS   (8192u * 4096u)
#define W_ELEMS   (3u * 2048u * 4096u)
#define A_VEC4    (A_ELEMS / 4u)
#define TOT_VEC4  ((A_ELEMS + W_ELEMS) / 4u)

// ---------------- scratch: single array so 32-bit byte offsets address A and W ----------
__device__ __align__(1024) __half g_AW[A_ELEMS + W_ELEMS];

// ---------------- helpers ----------------
static __device__ __forceinline__ uint32_t smem_u32(const void* p) {
    uint32_t a;
    asm("{ .reg .u64 t; cvta.to.shared.u64 t, %1; cvt.u32.u64 %0, t; }" : "=r"(a) : "l"(p));
    return a;
}
static __device__ __forceinline__ void cp16(uint32_t dst, const void* src) {
    asm volatile("cp.async.cg.shared.global [%0], [%1], 16;" :: "r"(dst), "l"(src) : "memory");
}
static __device__ __forceinline__ void ldsm4(uint32_t* r, uint32_t addr) {
    asm volatile("ldmatrix.sync.aligned.m8n8.x4.shared.b16 {%0,%1,%2,%3}, [%4];"
                 : "=r"(r[0]), "=r"(r[1]), "=r"(r[2]), "=r"(r[3]) : "r"(addr));
}
static __device__ __forceinline__ void mma16816(float* c4, const uint32_t* a,
                                                uint32_t b0, uint32_t b1) {
    asm volatile(
        "mma.sync.aligned.m16n8k16.row.col.f32.f16.f16.f32 "
        "{%0,%1,%2,%3}, {%4,%5,%6,%7}, {%8,%9}, {%0,%1,%2,%3};"
        : "+f"(c4[0]), "+f"(c4[1]), "+f"(c4[2]), "+f"(c4[3])
        : "r"(a[0]), "r"(a[1]), "r"(a[2]), "r"(a[3]), "r"(b0), "r"(b1));
}
static __device__ __forceinline__ float sigf(float x) {
    return __fdividef(1.f, 1.f + __expf(-x));
}
static __device__ __forceinline__ float tanhe(float x) {
    float t = __expf(2.f * x);
    return __fdividef(t - 1.f, t + 1.f);
}
static __device__ __forceinline__ uint32_t sw128(uint32_t off) {
    return off ^ ((off >> 3) & 0x70);
}

// ---------------- kernel 1: fp32 -> fp16 pack into K-concatenated g_AW ----------------
__global__ void __launch_bounds__(256)
lstm_conv_kernel(const float* __restrict__ x,   const float* __restrict__ h,
                 const float* __restrict__ Wix, const float* __restrict__ Wmx,
                 const float* __restrict__ Wox, const float* __restrict__ Wih,
                 const float* __restrict__ Wmh, const float* __restrict__ Woh)
{
    const size_t i = (size_t)blockIdx.x * 256 + threadIdx.x;   // vec4 index
    const float* src;
    __half* dst;
    if (i < A_VEC4) {
        size_t e = i << 2;                 // element in [0, A_ELEMS)
        size_t m = e >> 12, k = e & 4095;
        src = (k < 2048 ? x : h) + m * 2048 + (k & 2047);
        dst = g_AW + e;
    } else {
        size_t e = (i - A_VEC4) << 2;      // element in [0, W_ELEMS)
        size_t g = e >> 23;                // each gate = 2^23 elems
        size_t r = e & 8388607;
        size_t n = r >> 12, k = r & 4095;
        const float* Wx = (g == 0 ? Wix : (g == 1 ? Wmx : Wox));
        const float* Wh2 = (g == 0 ? Wih : (g == 1 ? Wmh : Woh));
        src = (k < 2048 ? Wx : Wh2) + n * 2048 + (k & 2047);
        dst = g_AW + A_ELEMS + e;
    }
    float4 v = *(const float4*)src;
    __half2 p0 = __floats2half2_rn(v.x, v.y);
    __half2 p1 = __floats2half2_rn(v.z, v.w);
    uint2 pk;
    pk.x = *(const uint32_t*)&p0;
    pk.y = *(const uint32_t*)&p1;
    *(uint2*)dst = pk;
}

// ---------------- kernel 2: fused 3-gate warp-MMA GEMM + LSTM epilogue ----------------
__global__ void __launch_bounds__(256, 1)
lstm_gemm_kernel(const float* __restrict__ c,
                 const float* __restrict__ bix, const float* __restrict__ bmx,
                 const float* __restrict__ box_,
                 const float* __restrict__ bih, const float* __restrict__ bmh,
                 const float* __restrict__ boh,
                 float* __restrict__ out)
{
    extern __shared__ char smem[];
    const uint32_t sb = smem_u32(smem);
    float* sbias = (float*)smem;                  // [3][64] gate bias sums

    const int tid  = threadIdx.x;
    const int wid  = tid >> 5;
    const int lane = tid & 31;
    const int wm   = wid & 1;        // 2 warps along M (64 rows each)
    const int wn   = wid >> 1;       // 4 warps along N (16 cols each)

    const int n0 = (blockIdx.x & 31) << 6;    // n fastest -> W stays L2-resident
    const int m0 = (int)(blockIdx.x >> 5) << 7;

    if (tid < 192) {
        int g  = tid >> 6;
        int nl = tid & 63;
        int n  = n0 + nl;
        const float* bx = (g == 0 ? bix : (g == 1 ? bmx : box_));
        const float* bh = (g == 0 ? bih : (g == 1 ? bmh : boh));
        sbias[tid] = bx[n] + bh[n];
    }

    // ---- producer address precompute: 10 x 16B chunks per 64-wide sub-chunk ----
    uint32_t pSrc[10];   // byte offset into g_AW (k=0)
    uint32_t pDst[10];   // swizzled offset within a sub-chunk (constant per stage)
#pragma unroll
    for (int i = 0; i < 10; ++i) {
        int ch = tid + i * 256;                  // 0..2559
        if (ch < 1024) {                         // A tile: 128 rows x 8 chunks
            int r  = ch >> 3;
            int cc = ch & 7;
            pSrc[i] = (uint32_t)(((uint32_t)(m0 + r) * 4096u + (uint32_t)cc * 8u) * 2u);
            pDst[i] = sw128((uint32_t)((r << 7) + (cc << 4)));
        } else {                                 // B tiles: 3 x 64 rows x 8 chunks
            int b  = ch - 1024;
            int g  = b >> 9;
            int r  = (b & 511) >> 3;
            int cc = b & 7;
            pSrc[i] = (A_ELEMS + (uint32_t)g * 8388608u
                       + (uint32_t)(n0 + r) * 4096u + (uint32_t)cc * 8u) * 2u;
            pDst[i] = 16384u + (uint32_t)g * 8192u
                      + sw128((uint32_t)((r << 7) + (cc << 4)));
        }
    }
    const char* gbase = (const char*)g_AW;

    auto load_stage = [&](int s, int st) {
        const uint32_t stb = sb + 1024 + (uint32_t)st * STAGE_BYTES;
        const char* src = gbase + (size_t)s * 256;     // k advances 128 elems = 256 B
#pragma unroll
        for (int sub = 0; sub < 2; ++sub)
#pragma unroll
            for (int i = 0; i < 10; ++i)
                cp16(stb + (uint32_t)sub * SUB_BYTES + pDst[i],
                     src + pSrc[i] + sub * 128);
        asm volatile("cp.async.commit_group;" ::: "memory");
    };

    // ---- consumer addressing ----
    // Swizzle mask depends only on (row & 7) == (lane & 7), identical for every
    // A-block row (rA + i*16) and B row (rB) this thread touches.  Column
    // offset kcol = kbl + ks*32 has no carries (disjoint bits), so the exact
    // swizzled address is rowbase + (kcol ^ mask) -- swizzle correctly applied
    // per-k, with only rowbases hoisted (this was R7's bug: adding kb AFTER
    // the XOR carries into the row bits and walks out of the tile).
    const uint32_t kbl  = (uint32_t)((lane >> 4) << 4);
    const uint32_t mask = (uint32_t)((lane & 7) << 4);
    const int rA = wm * 64 + (lane & 15);
    const int rB = wn * 16 + (lane & 15);
    uint32_t baseA[4], baseB[3];
#pragma unroll
    for (int i = 0; i < 4; ++i)
        baseA[i] = (uint32_t)((rA + i * 16) << 7);
#pragma unroll
    for (int g = 0; g < 3; ++g)
        baseB[g] = 16384u + (uint32_t)g * 8192u + (uint32_t)(rB << 7);

    // ---- accumulators: [gate][m16 block][n8 block][4] ----
    float acc[3][4][2][4];
#pragma unroll
    for (int g = 0; g < 3; ++g)
#pragma unroll
        for (int i = 0; i < 4; ++i)
#pragma unroll
            for (int j = 0; j < 2; ++j)
#pragma unroll
                for (int v = 0; v < 4; ++v) acc[g][i][j][v] = 0.f;

    auto compute_stage = [&](int st) {
        const uint32_t stb = sb + 1024 + (uint32_t)st * STAGE_BYTES;
#pragma unroll
        for (int sub = 0; sub < 2; ++sub) {
            const uint32_t sbase = stb + (uint32_t)sub * SUB_BYTES;
#pragma unroll
            for (int ks = 0; ks < 4; ++ks) {
                const uint32_t xcol = (kbl + (uint32_t)(ks * 32)) ^ mask;
                uint32_t a[4][4];
#pragma unroll
                for (int i = 0; i < 4; ++i)
                    ldsm4(a[i], sbase + baseA[i] + xcol);
#pragma unroll
                for (int g = 0; g < 3; ++g) {
                    uint32_t b[4];
                    ldsm4(b, sbase + baseB[g] + xcol);
#pragma unroll
                    for (int i = 0; i < 4; ++i) {
                        mma16816(acc[g][i][0], a[i], b[0], b[2]);
                        mma16816(acc[g][i][1], a[i], b[1], b[3]);
                    }
                }
            }
        }
    };

    // ---- 2-stage pipeline, 32 iterations ----
    load_stage(0, 0);
    for (int s = 0; s < KITERS; ++s) {
        asm volatile("cp.async.wait_group 0;" ::: "memory");
        __syncthreads();
        if (s + 1 < KITERS) load_stage(s + 1, (s + 1) & 1);
        compute_stage(s & 1);
    }

    // ---- fused LSTM epilogue (fully register-local) ----
    const int quad = lane >> 2;
    const int tc   = lane & 3;
#pragma unroll
    for (int i = 0; i < 4; ++i) {
#pragma unroll
        for (int hh = 0; hh < 2; ++hh) {
            const int m = m0 + wm * 64 + i * 16 + quad + hh * 8;
            const float* crow = c   + (size_t)m * DH;
            float*       hrow = out + (size_t)m * DH;
            float*       nrow = out + (size_t)8192 * DH + (size_t)m * DH;
#pragma unroll
            for (int j = 0; j < 2; ++j) {
                const int nl = wn * 16 + j * 8 + tc * 2;
                const int n  = n0 + nl;
                float2 c2 = *(const float2*)(crow + n);
                float hn[2], cn[2];
#pragma unroll
                for (int e = 0; e < 2; ++e) {
                    float gi = acc[0][i][j][hh * 2 + e] + sbias[nl + e];
                    float gm = acc[1][i][j][hh * 2 + e] + sbias[64 + nl + e];
                    float go = acc[2][i][j][hh * 2 + e] + sbias[128 + nl + e];
                    float is = sigf(gi);
                    float fs = sigf(gm);
                    float ms = tanhe(gm);
                    float os = sigf(go);
                    float cold = (e == 0 ? c2.x : c2.y);
                    float cc = fs * cold + is * ms;
                    cn[e] = cc;
                    hn[e] = os * tanhe(cc);
                }
                *(float2*)(hrow + n) = make_float2(hn[0], hn[1]);
                *(float2*)(nrow + n) = make_float2(cn[0], cn[1]);
            }
        }
    }
}

// ---------------- launch ----------------
extern "C" void kernel_launch(void* const* d_in, const int* in_sizes, int n_in,
                              void* d_out, int out_size) {
    const float* x   = (const float*)d_in[0];
    const float* h   = (const float*)d_in[1];
    const float* c   = (const float*)d_in[2];
    const float* Wix = (const float*)d_in[3];
    const float* bix = (const float*)d_in[4];
    const float* Wmx = (const float*)d_in[5];
    const float* bmx = (const float*)d_in[6];
    const float* Wox = (const float*)d_in[7];
    const float* box_= (const float*)d_in[8];
    const float* Wih = (const float*)d_in[9];
    const float* bih = (const float*)d_in[10];
    const float* Wmh = (const float*)d_in[11];
    const float* bmh = (const float*)d_in[12];
    const float* Woh = (const float*)d_in[13];
    const float* boh = (const float*)d_in[14];
    float* out = (float*)d_out;

    cudaFuncSetAttribute(lstm_gemm_kernel,
                         cudaFuncAttributeMaxDynamicSharedMemorySize, SMEM_TOTAL);

    lstm_conv_kernel<<<TOT_VEC4 / 256, 256>>>(x, h, Wix, Wmx, Wox, Wih, Wmh, Woh);
    lstm_gemm_kernel<<<2048, 256, SMEM_TOTAL>>>(c, bix, bmx, box_, bih, bmh, boh, out);
}